// round 13
// baseline (speedup 1.0000x reference)
#include <cuda_runtime.h>
#include <cuda_bf16.h>
#include <math.h>

// ----------------------------------------------------------------------------
// BlobStore — bit-exact replication of the reference fp32 scoring chain:
//   q2_n    = sum_d fl(q_d^2) * iv[n,d]            (sequential d-ascending FFMA)
//   cross_n = sum_d q_d * fl(mu*iv)[n,d]           (sequential d-ascending FFMA)
//   mahal   = (q2 - 2*cross) + m2                  (exact jnp op order)
//   t       = -0.5 * mahal
//   score   = __nv_expf(t / tau) * alpha
// Coarse top-32 by (t desc, idx asc), exact-score refinement, top-k by
// (score desc, idx asc) == jax.lax.top_k.
//
// R13 vs R12 (2646us): GEMM occupancy/latency fix.
//   * thread tile 2q x 8n: 32 acc regs (was 64); total ~80 regs.
//   * launch_bounds(256,3): 3 CTAs/SM, 6 warps/SMSP (was 4) — hides L2 W-fetch.
//   * A via single LDS.128 of pre-duplicated (v,v) pairs per chain per d-step.
//   * Arithmetic bit-identical to R12 (rel_err must stay 5.114588e-4).
// ----------------------------------------------------------------------------

extern "C" __device__ float __nv_expf(float);   // libdevice, immune to fast-math

typedef unsigned long long ull;

#define DS   64
#define NMAX 131072
#define BMAX 1024
#define NCAND 32

__device__ float g_Wiv[(size_t)DS * NMAX];   // iv rows, [d][n]
__device__ float g_Wmu[(size_t)DS * NMAX];   // mu*iv rows, [d][n]
__device__ float g_m2[NMAX];
__device__ float g_alpha[NMAX];
__device__ ull   g_Xq2d[(size_t)DS * BMAX];  // (q^2, q^2) pairs, [d][b]
__device__ ull   g_Xqd [(size_t)DS * BMAX];  // (q, q) pairs, [d][b]
__device__ float g_T[(size_t)BMAX * NMAX];   // t = -0.5*mahal (512 MB)
__device__ int   g_topidx[BMAX * NCAND];
__device__ float g_topval[BMAX * NCAND];

__device__ __forceinline__ ull pk2(float lo, float hi) {
    ull r; asm("mov.b64 %0, {%1, %2};" : "=l"(r) : "f"(lo), "f"(hi)); return r;
}
__device__ __forceinline__ void upk2(ull v, float& lo, float& hi) {
    asm("mov.b64 {%0, %1}, %2;" : "=f"(lo), "=f"(hi) : "l"(v));
}
__device__ __forceinline__ void ffma2(ull& d, ull a, ull b) {
    asm("fma.rn.f32x2 %0, %1, %2, %0;" : "+l"(d) : "l"(a), "l"(b));
}

// ---------------------------------------------------------------------------
// prep_blob: coalesced read + smem transpose + coalesced column writes.
// ---------------------------------------------------------------------------
#define PB_TILE 32
__global__ __launch_bounds__(256)
void prep_blob(const float* __restrict__ mu,
               const float* __restrict__ lv,
               const float* __restrict__ ra, int N) {
    __shared__ float s_iv [PB_TILE][DS + 1];
    __shared__ float s_miv[PB_TILE][DS + 1];
    __shared__ float s_m2t[PB_TILE][DS + 1];
    const int n0 = blockIdx.x * PB_TILE;
    const int tid = threadIdx.x;

    for (int i = tid; i < PB_TILE * DS; i += 256) {
        int nl = i >> 6, d = i & 63;
        float m  = mu[(size_t)(n0 + nl) * DS + d];
        float iv = __nv_expf(-lv[(size_t)(n0 + nl) * DS + d]);
        s_iv[nl][d]  = iv;
        s_miv[nl][d] = __fmul_rn(m, iv);
        s_m2t[nl][d] = __fmul_rn(__fmul_rn(m, m), iv);
    }
    __syncthreads();

    if (tid < PB_TILE) {
        float m2 = 0.f;
        #pragma unroll 8
        for (int d = 0; d < DS; ++d) m2 = __fadd_rn(m2, s_m2t[tid][d]);
        g_m2[n0 + tid] = m2;
        float x = ra[n0 + tid];
        g_alpha[n0 + tid] = __fdiv_rn(1.f, __fadd_rn(1.f, __nv_expf(-x)));
    }
    __syncthreads();

    for (int i = tid; i < PB_TILE * DS; i += 256) {
        int d = i >> 5, nl = i & 31;
        g_Wiv[(size_t)d * N + n0 + nl] = s_iv[nl][d];
        g_Wmu[(size_t)d * N + n0 + nl] = s_miv[nl][d];
    }
}

__global__ void prep_query(const float* __restrict__ q, int B) {
    int i = blockIdx.x * blockDim.x + threadIdx.x;
    if (i >= DS * B) return;
    int d = i / B, b = i - d * B;
    float v = q[(size_t)b * DS + d];
    float v2 = __fmul_rn(v, v);
    g_Xq2d[i] = pk2(v2, v2);
    g_Xqd[i]  = pk2(v, v);
}

// ---------------------------------------------------------------------------
// t-GEMM: block 32q x 128n, thread tile 2q x 8n (f32x2). 32 acc regs.
// Even/odd alternating W register sets (distance-1 prefetch, zero copies).
// 3 CTAs/SM (6 warps/SMSP) hides the L2 W-fetch latency.
// ---------------------------------------------------------------------------
#define FMA_BLOCK(W1A, W1B, W2A, W2B, DD)                                     \
    {                                                                         \
        ulonglong2 bq2 = *(const ulonglong2*)&s_q2d[(DD) * 32 + ty * 2];      \
        ulonglong2 bq  = *(const ulonglong2*)&s_qd [(DD) * 32 + ty * 2];      \
        ffma2(a1[0][0], bq2.x, (W1A).x); ffma2(a1[0][1], bq2.x, (W1A).y);     \
        ffma2(a1[0][2], bq2.x, (W1B).x); ffma2(a1[0][3], bq2.x, (W1B).y);     \
        ffma2(a1[1][0], bq2.y, (W1A).x); ffma2(a1[1][1], bq2.y, (W1A).y);     \
        ffma2(a1[1][2], bq2.y, (W1B).x); ffma2(a1[1][3], bq2.y, (W1B).y);     \
        ffma2(a2[0][0], bq.x,  (W2A).x); ffma2(a2[0][1], bq.x,  (W2A).y);     \
        ffma2(a2[0][2], bq.x,  (W2B).x); ffma2(a2[0][3], bq.x,  (W2B).y);     \
        ffma2(a2[1][0], bq.y,  (W2A).x); ffma2(a2[1][1], bq.y,  (W2A).y);     \
        ffma2(a2[1][2], bq.y,  (W2B).x); ffma2(a2[1][3], bq.y,  (W2B).y);     \
    }

__global__ __launch_bounds__(256, 3)
void gemm_t_kernel(int B, int N) {
    __shared__ ull s_q2d[DS * 32];   // [64d][32q] pairs, 16 KB
    __shared__ ull s_qd [DS * 32];   // 16 KB
    const int tid = threadIdx.x;
    const int tx = tid & 15, ty = tid >> 4;
    const int qb = blockIdx.x * 32, nb = blockIdx.y * 128;

    for (int i = tid; i < DS * 32; i += 256) {
        int d = i >> 5, j = i & 31;
        s_q2d[i] = g_Xq2d[(size_t)d * B + qb + j];
        s_qd[i]  = g_Xqd [(size_t)d * B + qb + j];
    }
    __syncthreads();

    const int n0 = nb + tx * 8;
    ull a1[2][4], a2[2][4];
    #pragma unroll
    for (int qi = 0; qi < 2; ++qi)
        #pragma unroll
        for (int ni = 0; ni < 4; ++ni) { a1[qi][ni] = 0ull; a2[qi][ni] = 0ull; }

    const float* piv = g_Wiv + n0;
    const float* pmu = g_Wmu + n0;

    // even set (d=0)
    ulonglong2 e1a = *(const ulonglong2*)(piv);
    ulonglong2 e1b = *(const ulonglong2*)(piv + 4);
    ulonglong2 e2a = *(const ulonglong2*)(pmu);
    ulonglong2 e2b = *(const ulonglong2*)(pmu + 4);

    #pragma unroll 1
    for (int d = 0; d < DS; d += 2) {
        // prefetch odd row (d+1) — always valid (last odd row = 63)
        ulonglong2 o1a = *(const ulonglong2*)(piv + N);
        ulonglong2 o1b = *(const ulonglong2*)(piv + N + 4);
        ulonglong2 o2a = *(const ulonglong2*)(pmu + N);
        ulonglong2 o2b = *(const ulonglong2*)(pmu + N + 4);

        FMA_BLOCK(e1a, e1b, e2a, e2b, d);      // consume even d

        piv += 2 * (size_t)N;
        pmu += 2 * (size_t)N;
        if (d + 2 < DS) {                       // prefetch next even row
            e1a = *(const ulonglong2*)(piv);
            e1b = *(const ulonglong2*)(piv + 4);
            e2a = *(const ulonglong2*)(pmu);
            e2b = *(const ulonglong2*)(pmu + 4);
        }

        FMA_BLOCK(o1a, o1b, o2a, o2b, d + 1);  // consume odd d+1
    }

    float m2v[8];
    { float4 ma = *(const float4*)(g_m2 + n0);
      float4 mb = *(const float4*)(g_m2 + n0 + 4);
      m2v[0]=ma.x; m2v[1]=ma.y; m2v[2]=ma.z; m2v[3]=ma.w;
      m2v[4]=mb.x; m2v[5]=mb.y; m2v[6]=mb.z; m2v[7]=mb.w; }

    #pragma unroll
    for (int qi = 0; qi < 2; ++qi) {
        float o[8];
        #pragma unroll
        for (int ni = 0; ni < 4; ++ni) {
            float x1l, x1h, x2l, x2h;
            upk2(a1[qi][ni], x1l, x1h);
            upk2(a2[qi][ni], x2l, x2h);
            // t = -0.5 * ((q2 - 2*cross) + m2)   — exact jnp op order
            o[2*ni]   = __fmul_rn(-0.5f, __fadd_rn(__fsub_rn(x1l, __fmul_rn(2.0f, x2l)), m2v[2*ni]));
            o[2*ni+1] = __fmul_rn(-0.5f, __fadd_rn(__fsub_rn(x1h, __fmul_rn(2.0f, x2h)), m2v[2*ni+1]));
        }
        size_t row = (size_t)(qb + ty * 2 + qi);
        float4* dst = (float4*)(g_T + row * N + n0);
        dst[0] = make_float4(o[0], o[1], o[2], o[3]);
        dst[1] = make_float4(o[4], o[5], o[6], o[7]);
    }
}

// ---------------------------------------------------------------------------
// Top-32 by (t desc, idx asc): per-thread sorted-16 scan, block merge.
// ---------------------------------------------------------------------------
__device__ __forceinline__ void insert16(float* val, int* idx, float s, int n) {
    float cv = s; int ci = n;
    #pragma unroll
    for (int j = 0; j < 16; ++j) {
        bool better = (cv > val[j]) || (cv == val[j] && ci < idx[j]);
        if (better) {
            float tv = val[j]; val[j] = cv; cv = tv;
            int   ti = idx[j]; idx[j] = ci; ci = ti;
        }
    }
}

__global__ __launch_bounds__(256)
void topk_kernel(int B, int N) {
    const int b = blockIdx.x;
    const int tid = threadIdx.x;
    const float* row = g_T + (size_t)b * N;

    float val[16]; int idx[16];
    #pragma unroll
    for (int j = 0; j < 16; ++j) { val[j] = -INFINITY; idx[j] = 0x7fffffff; }

    for (int base = tid * 4; base < N; base += 1024) {
        float4 v = *(const float4*)(row + base);
        if (v.x > val[15] || (v.x == val[15] && base + 0 < idx[15])) insert16(val, idx, v.x, base + 0);
        if (v.y > val[15] || (v.y == val[15] && base + 1 < idx[15])) insert16(val, idx, v.y, base + 1);
        if (v.z > val[15] || (v.z == val[15] && base + 2 < idx[15])) insert16(val, idx, v.z, base + 2);
        if (v.w > val[15] || (v.w == val[15] && base + 3 < idx[15])) insert16(val, idx, v.w, base + 3);
    }

    __shared__ float sval[4096];
    __shared__ int   sidx[4096];
    __shared__ float rv[8];
    __shared__ int   ri[8], rs[8];
    #pragma unroll
    for (int j = 0; j < 16; ++j) { sval[tid * 16 + j] = val[j]; sidx[tid * 16 + j] = idx[j]; }
    __syncthreads();

    for (int r = 0; r < NCAND; ++r) {
        float bv = -INFINITY; int bi = 0x7fffffff, bs = -1;
        for (int j = tid; j < 4096; j += 256) {
            float v = sval[j]; int id = sidx[j];
            if (v > bv || (v == bv && id < bi)) { bv = v; bi = id; bs = j; }
        }
        #pragma unroll
        for (int off = 16; off; off >>= 1) {
            float ov = __shfl_down_sync(0xffffffffu, bv, off);
            int   oi = __shfl_down_sync(0xffffffffu, bi, off);
            int   os = __shfl_down_sync(0xffffffffu, bs, off);
            if (ov > bv || (ov == bv && oi < bi)) { bv = ov; bi = oi; bs = os; }
        }
        if ((tid & 31) == 0) { rv[tid >> 5] = bv; ri[tid >> 5] = bi; rs[tid >> 5] = bs; }
        __syncthreads();
        if (tid == 0) {
            float fbv = rv[0]; int fbi = ri[0], fbs = rs[0];
            #pragma unroll
            for (int w = 1; w < 8; ++w)
                if (rv[w] > fbv || (rv[w] == fbv && ri[w] < fbi)) { fbv = rv[w]; fbi = ri[w]; fbs = rs[w]; }
            g_topidx[b * NCAND + r] = fbi;
            g_topval[b * NCAND + r] = fbv;
            sval[fbs] = -INFINITY;
            sidx[fbs] = 0x7fffffff;
        }
        __syncthreads();
    }
}

// ---------------------------------------------------------------------------
// Refine 32 candidates with the exact reference score, pick k, rescore,
// composite, feature reduction, t_residual.
// ---------------------------------------------------------------------------
__global__ __launch_bounds__(256)
void composite_kernel(const float* __restrict__ q,
                      const float* __restrict__ mu,
                      const float* __restrict__ lv,
                      const float* __restrict__ ra,
                      const float* __restrict__ feat,
                      const float* __restrict__ lt,
                      const int* __restrict__ kptr,
                      float* __restrict__ out,
                      int B, int dF, int out_size) {
    const int b = blockIdx.x;
    const int tid = threadIdx.x;
    const int warp = tid >> 5, lane = tid & 31;

    __shared__ float cs[NCAND];
    __shared__ int   ci[NCAND];
    __shared__ int   s_ord[16];
    __shared__ float s_eff[16];
    __shared__ float s_w[16];
    __shared__ float s_tres;

    int kk = kptr ? *kptr : 16;
    if (kk > 16) kk = 16;
    if (kk < 1)  kk = 1;
    float tau = __nv_expf(lt[0]);
    float cap = (float)(0.3 / (double)kk);   // T_MAX / k

    if (tid < NCAND) {
        int   id = g_topidx[b * NCAND + tid];
        float t  = g_topval[b * NCAND + tid];
        cs[tid] = __fmul_rn(__nv_expf(__fdiv_rn(t, tau)), g_alpha[id]);
        ci[tid] = id;
    }
    __syncthreads();

    if (tid == 0) {
        for (int r = 0; r < kk; ++r) {
            int best = r;
            for (int j = r + 1; j < NCAND; ++j)
                if (cs[j] > cs[best] || (cs[j] == cs[best] && ci[j] < ci[best])) best = j;
            float tv = cs[r]; cs[r] = cs[best]; cs[best] = tv;
            int   ti = ci[r]; ci[r] = ci[best]; ci[best] = ti;
            s_ord[r] = ci[r];
        }
    }
    __syncthreads();

    for (int i = warp; i < kk; i += 8) {
        int n = s_ord[i];
        float d0 = q[(size_t)b * DS + lane]      - mu[(size_t)n * DS + lane];
        float d1 = q[(size_t)b * DS + lane + 32] - mu[(size_t)n * DS + lane + 32];
        float iv0 = __nv_expf(-lv[(size_t)n * DS + lane]);
        float iv1 = __nv_expf(-lv[(size_t)n * DS + lane + 32]);
        float s = d0 * d0 * iv0 + d1 * d1 * iv1;
        #pragma unroll
        for (int off = 16; off; off >>= 1) s += __shfl_xor_sync(0xffffffffu, s, off);
        if (lane == 0) {
            float K = __nv_expf(__fdiv_rn(-0.5f * s, tau));
            float a = __fdiv_rn(1.f, 1.f + __nv_expf(-ra[n]));
            s_eff[i] = fminf(a * K, cap);
        }
    }
    __syncthreads();

    if (tid == 0) {
        float logT = 0.f;
        for (int i = 0; i < kk; ++i) {
            float e = s_eff[i];
            s_w[i] = e * __nv_expf(logT);
            logT += log1pf(-fminf(e, 1.f - 1e-6f));
        }
        s_tres = __nv_expf(logT);
    }
    __syncthreads();

    for (int d = tid; d < dF; d += 256) {
        float acc = 0.f;
        for (int i = 0; i < kk; ++i)
            acc += s_w[i] * feat[(size_t)s_ord[i] * dF + d];
        out[(size_t)b * dF + d] = acc;
    }
    if (tid == 0 && out_size >= B * dF + B)
        out[(size_t)B * dF + b] = s_tres;
}

// ---------------------------------------------------------------------------
extern "C" void kernel_launch(void* const* d_in, const int* in_sizes, int n_in,
                              void* d_out, int out_size) {
    const float* query     = (const float*)d_in[0];
    const float* mu        = (const float*)d_in[1];
    const float* log_var   = (const float*)d_in[2];
    const float* raw_alpha = (const float*)d_in[3];
    const float* features  = (const float*)d_in[4];
    const float* log_tau   = (const float*)d_in[5];
    const int*   kptr      = (n_in >= 7) ? (const int*)d_in[6] : nullptr;

    int B  = in_sizes[0] / DS;     // 1024
    int N  = in_sizes[1] / DS;     // 131072
    int dF = in_sizes[4] / N;      // 256
    float* out = (float*)d_out;

    prep_blob<<<N / PB_TILE, 256>>>(mu, log_var, raw_alpha, N);
    prep_query<<<(DS * B + 255) / 256, 256>>>(query, B);

    dim3 ggrid(B / 32, N / 128);   // q-tiles fast => W reuse in L2
    gemm_t_kernel<<<ggrid, 256>>>(B, N);

    topk_kernel<<<B, 256>>>(B, N);

    composite_kernel<<<B, 256>>>(query, mu, log_var, raw_alpha, features,
                                 log_tau, kptr, out, B, dF, out_size);
}

// round 17
// speedup vs baseline: 1.3890x; 1.3890x over previous
#include <cuda_runtime.h>
#include <cuda_bf16.h>
#include <math.h>
#include <cstdint>

// ----------------------------------------------------------------------------
// BlobStore — bit-exact replication of the reference fp32 scoring chain:
//   q2_n    = sum_d fl(q_d^2) * iv[n,d]            (sequential d-ascending FFMA)
//   cross_n = sum_d q_d * fl(mu*iv)[n,d]           (sequential d-ascending FFMA)
//   mahal   = (q2 - 2*cross) + m2                  (exact jnp op order)
//   t       = -0.5 * mahal
//   score   = __nv_expf(t / tau) * alpha
// Coarse top-32 by (t desc, idx asc), exact-score refinement, top-k by
// (score desc, idx asc) == jax.lax.top_k.
//
// R17 == R15/R16 (infra retry #2): GEMM was L2-BW-bound on redundant per-warp
// W loads (R13's tile-shrink regression matched the traffic model). Fix:
// cp.async double-buffered smem staging — W fetched once per CTA.
// Block 64q x 128n, 8-d chunks, 32KB smem, 2 CTAs/SM. Arithmetic identical.
// ----------------------------------------------------------------------------

extern "C" __device__ float __nv_expf(float);   // libdevice, immune to fast-math

typedef unsigned long long ull;

#define DS   64
#define NMAX 131072
#define BMAX 1024
#define NCAND 32
#define BD   8                 // d-rows per staged chunk
#define NCH  (DS / BD)         // 8 chunks

__device__ float g_Wiv[(size_t)DS * NMAX];   // iv rows, [d][n]
__device__ float g_Wmu[(size_t)DS * NMAX];   // mu*iv rows, [d][n]
__device__ float g_m2[NMAX];
__device__ float g_alpha[NMAX];
__device__ ull   g_Xq2d[(size_t)DS * BMAX];  // (q^2, q^2) pairs, [d][b]
__device__ ull   g_Xqd [(size_t)DS * BMAX];  // (q, q) pairs, [d][b]
__device__ float g_T[(size_t)BMAX * NMAX];   // t = -0.5*mahal (512 MB)
__device__ int   g_topidx[BMAX * NCAND];
__device__ float g_topval[BMAX * NCAND];

__device__ __forceinline__ ull pk2(float lo, float hi) {
    ull r; asm("mov.b64 %0, {%1, %2};" : "=l"(r) : "f"(lo), "f"(hi)); return r;
}
__device__ __forceinline__ void upk2(ull v, float& lo, float& hi) {
    asm("mov.b64 {%0, %1}, %2;" : "=f"(lo), "=f"(hi) : "l"(v));
}
__device__ __forceinline__ void ffma2(ull& d, ull a, ull b) {
    asm("fma.rn.f32x2 %0, %1, %2, %0;" : "+l"(d) : "l"(a), "l"(b));
}
__device__ __forceinline__ void cp16(void* smem_dst, const void* gsrc) {
    unsigned int d = (unsigned int)__cvta_generic_to_shared(smem_dst);
    asm volatile("cp.async.cg.shared.global [%0], [%1], 16;" :: "r"(d), "l"(gsrc));
}

// ---------------------------------------------------------------------------
// prep_blob: coalesced read + smem transpose + coalesced column writes.
// ---------------------------------------------------------------------------
#define PB_TILE 32
__global__ __launch_bounds__(256)
void prep_blob(const float* __restrict__ mu,
               const float* __restrict__ lv,
               const float* __restrict__ ra, int N) {
    __shared__ float s_iv [PB_TILE][DS + 1];
    __shared__ float s_miv[PB_TILE][DS + 1];
    __shared__ float s_m2t[PB_TILE][DS + 1];
    const int n0 = blockIdx.x * PB_TILE;
    const int tid = threadIdx.x;

    for (int i = tid; i < PB_TILE * DS; i += 256) {
        int nl = i >> 6, d = i & 63;
        float m  = mu[(size_t)(n0 + nl) * DS + d];
        float iv = __nv_expf(-lv[(size_t)(n0 + nl) * DS + d]);
        s_iv[nl][d]  = iv;
        s_miv[nl][d] = __fmul_rn(m, iv);
        s_m2t[nl][d] = __fmul_rn(__fmul_rn(m, m), iv);
    }
    __syncthreads();

    if (tid < PB_TILE) {
        float m2 = 0.f;
        #pragma unroll 8
        for (int d = 0; d < DS; ++d) m2 = __fadd_rn(m2, s_m2t[tid][d]);
        g_m2[n0 + tid] = m2;
        float x = ra[n0 + tid];
        g_alpha[n0 + tid] = __fdiv_rn(1.f, __fadd_rn(1.f, __nv_expf(-x)));
    }
    __syncthreads();

    for (int i = tid; i < PB_TILE * DS; i += 256) {
        int d = i >> 5, nl = i & 31;
        g_Wiv[(size_t)d * N + n0 + nl] = s_iv[nl][d];
        g_Wmu[(size_t)d * N + n0 + nl] = s_miv[nl][d];
    }
}

__global__ void prep_query(const float* __restrict__ q, int B) {
    int i = blockIdx.x * blockDim.x + threadIdx.x;
    if (i >= DS * B) return;
    int d = i / B, b = i - d * B;
    float v = q[(size_t)b * DS + d];
    float v2 = __fmul_rn(v, v);
    g_Xq2d[i] = pk2(v2, v2);
    g_Xqd[i]  = pk2(v, v);
}

// ---------------------------------------------------------------------------
// t-GEMM: block 64q x 128n, thread 4q x 8n, cp.async double-buffered smem
// staging of W rows (once per CTA) and A pairs. Bit-identical accumulation.
// ---------------------------------------------------------------------------
__global__ __launch_bounds__(256, 2)
void gemm_t_kernel(int B, int N) {
    __shared__ float s_Wiv[2][BD][128];
    __shared__ float s_Wmu[2][BD][128];
    __shared__ ull   s_A2 [2][BD][64];
    __shared__ ull   s_Aq [2][BD][64];

    const int tid = threadIdx.x;
    const int tx = tid & 15, ty = tid >> 4;
    const int qb = blockIdx.x * 64, nb = blockIdx.y * 128;

    const int sd  = tid >> 5;        // 0..7  (d-row within chunk)
    const int sseg = tid & 31;       // 0..31 (16B segment)

    // stage chunk c into buffer buf (each thread: 4 x 16B cp.async)
    #define STAGE(bufi, c)                                                       \
    {                                                                            \
        int D = (c) * BD + sd;                                                   \
        cp16(&s_Wiv[bufi][sd][sseg * 4], g_Wiv + (size_t)D * N + nb + sseg * 4); \
        cp16(&s_Wmu[bufi][sd][sseg * 4], g_Wmu + (size_t)D * N + nb + sseg * 4); \
        cp16(&s_A2 [bufi][sd][sseg * 2], g_Xq2d + (size_t)D * B + qb + sseg * 2);\
        cp16(&s_Aq [bufi][sd][sseg * 2], g_Xqd  + (size_t)D * B + qb + sseg * 2);\
        asm volatile("cp.async.commit_group;");                                  \
    }

    ull a1[4][4], a2[4][4];
    #pragma unroll
    for (int qi = 0; qi < 4; ++qi)
        #pragma unroll
        for (int ni = 0; ni < 4; ++ni) { a1[qi][ni] = 0ull; a2[qi][ni] = 0ull; }

    STAGE(0, 0);

    #pragma unroll 1
    for (int c = 0; c < NCH; ++c) {
        const int buf = c & 1;
        if (c + 1 < NCH) {
            STAGE((c + 1) & 1, c + 1);
            asm volatile("cp.async.wait_group 1;");
        } else {
            asm volatile("cp.async.wait_group 0;");
        }
        __syncthreads();

        #pragma unroll
        for (int dd = 0; dd < BD; ++dd) {
            ulonglong2 W1a = *(const ulonglong2*)&s_Wiv[buf][dd][tx * 8];
            ulonglong2 W1b = *(const ulonglong2*)&s_Wiv[buf][dd][tx * 8 + 4];
            ulonglong2 W2a = *(const ulonglong2*)&s_Wmu[buf][dd][tx * 8];
            ulonglong2 W2b = *(const ulonglong2*)&s_Wmu[buf][dd][tx * 8 + 4];
            ulonglong2 A2a = *(const ulonglong2*)&s_A2[buf][dd][ty * 4];
            ulonglong2 A2b = *(const ulonglong2*)&s_A2[buf][dd][ty * 4 + 2];
            ulonglong2 Aqa = *(const ulonglong2*)&s_Aq[buf][dd][ty * 4];
            ulonglong2 Aqb = *(const ulonglong2*)&s_Aq[buf][dd][ty * 4 + 2];

            ffma2(a1[0][0], A2a.x, W1a.x); ffma2(a1[0][1], A2a.x, W1a.y);
            ffma2(a1[0][2], A2a.x, W1b.x); ffma2(a1[0][3], A2a.x, W1b.y);
            ffma2(a1[1][0], A2a.y, W1a.x); ffma2(a1[1][1], A2a.y, W1a.y);
            ffma2(a1[1][2], A2a.y, W1b.x); ffma2(a1[1][3], A2a.y, W1b.y);
            ffma2(a1[2][0], A2b.x, W1a.x); ffma2(a1[2][1], A2b.x, W1a.y);
            ffma2(a1[2][2], A2b.x, W1b.x); ffma2(a1[2][3], A2b.x, W1b.y);
            ffma2(a1[3][0], A2b.y, W1a.x); ffma2(a1[3][1], A2b.y, W1a.y);
            ffma2(a1[3][2], A2b.y, W1b.x); ffma2(a1[3][3], A2b.y, W1b.y);

            ffma2(a2[0][0], Aqa.x, W2a.x); ffma2(a2[0][1], Aqa.x, W2a.y);
            ffma2(a2[0][2], Aqa.x, W2b.x); ffma2(a2[0][3], Aqa.x, W2b.y);
            ffma2(a2[1][0], Aqa.y, W2a.x); ffma2(a2[1][1], Aqa.y, W2a.y);
            ffma2(a2[1][2], Aqa.y, W2b.x); ffma2(a2[1][3], Aqa.y, W2b.y);
            ffma2(a2[2][0], Aqb.x, W2a.x); ffma2(a2[2][1], Aqb.x, W2a.y);
            ffma2(a2[2][2], Aqb.x, W2b.x); ffma2(a2[2][3], Aqb.x, W2b.y);
            ffma2(a2[3][0], Aqb.y, W2a.x); ffma2(a2[3][1], Aqb.y, W2a.y);
            ffma2(a2[3][2], Aqb.y, W2b.x); ffma2(a2[3][3], Aqb.y, W2b.y);
        }
        __syncthreads();
    }

    const int n0 = nb + tx * 8;
    float m2v[8];
    { float4 ma = *(const float4*)(g_m2 + n0);
      float4 mb = *(const float4*)(g_m2 + n0 + 4);
      m2v[0]=ma.x; m2v[1]=ma.y; m2v[2]=ma.z; m2v[3]=ma.w;
      m2v[4]=mb.x; m2v[5]=mb.y; m2v[6]=mb.z; m2v[7]=mb.w; }

    #pragma unroll
    for (int qi = 0; qi < 4; ++qi) {
        float o[8];
        #pragma unroll
        for (int ni = 0; ni < 4; ++ni) {
            float x1l, x1h, x2l, x2h;
            upk2(a1[qi][ni], x1l, x1h);
            upk2(a2[qi][ni], x2l, x2h);
            // t = -0.5 * ((q2 - 2*cross) + m2)   — exact jnp op order
            o[2*ni]   = __fmul_rn(-0.5f, __fadd_rn(__fsub_rn(x1l, __fmul_rn(2.0f, x2l)), m2v[2*ni]));
            o[2*ni+1] = __fmul_rn(-0.5f, __fadd_rn(__fsub_rn(x1h, __fmul_rn(2.0f, x2h)), m2v[2*ni+1]));
        }
        size_t row = (size_t)(qb + ty * 4 + qi);
        float4* dst = (float4*)(g_T + row * N + n0);
        dst[0] = make_float4(o[0], o[1], o[2], o[3]);
        dst[1] = make_float4(o[4], o[5], o[6], o[7]);
    }
}

// ---------------------------------------------------------------------------
// Top-32 by (t desc, idx asc): per-thread sorted-16 scan, block merge.
// ---------------------------------------------------------------------------
__device__ __forceinline__ void insert16(float* val, int* idx, float s, int n) {
    float cv = s; int ci = n;
    #pragma unroll
    for (int j = 0; j < 16; ++j) {
        bool better = (cv > val[j]) || (cv == val[j] && ci < idx[j]);
        if (better) {
            float tv = val[j]; val[j] = cv; cv = tv;
            int   ti = idx[j]; idx[j] = ci; ci = ti;
        }
    }
}

__global__ __launch_bounds__(256)
void topk_kernel(int B, int N) {
    const int b = blockIdx.x;
    const int tid = threadIdx.x;
    const float* row = g_T + (size_t)b * N;

    float val[16]; int idx[16];
    #pragma unroll
    for (int j = 0; j < 16; ++j) { val[j] = -INFINITY; idx[j] = 0x7fffffff; }

    for (int base = tid * 4; base < N; base += 1024) {
        float4 v = *(const float4*)(row + base);
        if (v.x > val[15] || (v.x == val[15] && base + 0 < idx[15])) insert16(val, idx, v.x, base + 0);
        if (v.y > val[15] || (v.y == val[15] && base + 1 < idx[15])) insert16(val, idx, v.y, base + 1);
        if (v.z > val[15] || (v.z == val[15] && base + 2 < idx[15])) insert16(val, idx, v.z, base + 2);
        if (v.w > val[15] || (v.w == val[15] && base + 3 < idx[15])) insert16(val, idx, v.w, base + 3);
    }

    __shared__ float sval[4096];
    __shared__ int   sidx[4096];
    __shared__ float rv[8];
    __shared__ int   ri[8], rs[8];
    #pragma unroll
    for (int j = 0; j < 16; ++j) { sval[tid * 16 + j] = val[j]; sidx[tid * 16 + j] = idx[j]; }
    __syncthreads();

    for (int r = 0; r < NCAND; ++r) {
        float bv = -INFINITY; int bi = 0x7fffffff, bs = -1;
        for (int j = tid; j < 4096; j += 256) {
            float v = sval[j]; int id = sidx[j];
            if (v > bv || (v == bv && id < bi)) { bv = v; bi = id; bs = j; }
        }
        #pragma unroll
        for (int off = 16; off; off >>= 1) {
            float ov = __shfl_down_sync(0xffffffffu, bv, off);
            int   oi = __shfl_down_sync(0xffffffffu, bi, off);
            int   os = __shfl_down_sync(0xffffffffu, bs, off);
            if (ov > bv || (ov == bv && oi < bi)) { bv = ov; bi = oi; bs = os; }
        }
        if ((tid & 31) == 0) { rv[tid >> 5] = bv; ri[tid >> 5] = bi; rs[tid >> 5] = bs; }
        __syncthreads();
        if (tid == 0) {
            float fbv = rv[0]; int fbi = ri[0], fbs = rs[0];
            #pragma unroll
            for (int w = 1; w < 8; ++w)
                if (rv[w] > fbv || (rv[w] == fbv && ri[w] < fbi)) { fbv = rv[w]; fbi = ri[w]; fbs = rs[w]; }
            g_topidx[b * NCAND + r] = fbi;
            g_topval[b * NCAND + r] = fbv;
            sval[fbs] = -INFINITY;
            sidx[fbs] = 0x7fffffff;
        }
        __syncthreads();
    }
}

// ---------------------------------------------------------------------------
// Refine 32 candidates with the exact reference score, pick k, rescore,
// composite, feature reduction, t_residual.
// ---------------------------------------------------------------------------
__global__ __launch_bounds__(256)
void composite_kernel(const float* __restrict__ q,
                      const float* __restrict__ mu,
                      const float* __restrict__ lv,
                      const float* __restrict__ ra,
                      const float* __restrict__ feat,
                      const float* __restrict__ lt,
                      const int* __restrict__ kptr,
                      float* __restrict__ out,
                      int B, int dF, int out_size) {
    const int b = blockIdx.x;
    const int tid = threadIdx.x;
    const int warp = tid >> 5, lane = tid & 31;

    __shared__ float cs[NCAND];
    __shared__ int   ci[NCAND];
    __shared__ int   s_ord[16];
    __shared__ float s_eff[16];
    __shared__ float s_w[16];
    __shared__ float s_tres;

    int kk = kptr ? *kptr : 16;
    if (kk > 16) kk = 16;
    if (kk < 1)  kk = 1;
    float tau = __nv_expf(lt[0]);
    float cap = (float)(0.3 / (double)kk);   // T_MAX / k

    if (tid < NCAND) {
        int   id = g_topidx[b * NCAND + tid];
        float t  = g_topval[b * NCAND + tid];
        cs[tid] = __fmul_rn(__nv_expf(__fdiv_rn(t, tau)), g_alpha[id]);
        ci[tid] = id;
    }
    __syncthreads();

    if (tid == 0) {
        for (int r = 0; r < kk; ++r) {
            int best = r;
            for (int j = r + 1; j < NCAND; ++j)
                if (cs[j] > cs[best] || (cs[j] == cs[best] && ci[j] < ci[best])) best = j;
            float tv = cs[r]; cs[r] = cs[best]; cs[best] = tv;
            int   ti = ci[r]; ci[r] = ci[best]; ci[best] = ti;
            s_ord[r] = ci[r];
        }
    }
    __syncthreads();

    for (int i = warp; i < kk; i += 8) {
        int n = s_ord[i];
        float d0 = q[(size_t)b * DS + lane]      - mu[(size_t)n * DS + lane];
        float d1 = q[(size_t)b * DS + lane + 32] - mu[(size_t)n * DS + lane + 32];
        float iv0 = __nv_expf(-lv[(size_t)n * DS + lane]);
        float iv1 = __nv_expf(-lv[(size_t)n * DS + lane + 32]);
        float s = d0 * d0 * iv0 + d1 * d1 * iv1;
        #pragma unroll
        for (int off = 16; off; off >>= 1) s += __shfl_xor_sync(0xffffffffu, s, off);
        if (lane == 0) {
            float K = __nv_expf(__fdiv_rn(-0.5f * s, tau));
            float a = __fdiv_rn(1.f, 1.f + __nv_expf(-ra[n]));
            s_eff[i] = fminf(a * K, cap);
        }
    }
    __syncthreads();

    if (tid == 0) {
        float logT = 0.f;
        for (int i = 0; i < kk; ++i) {
            float e = s_eff[i];
            s_w[i] = e * __nv_expf(logT);
            logT += log1pf(-fminf(e, 1.f - 1e-6f));
        }
        s_tres = __nv_expf(logT);
    }
    __syncthreads();

    for (int d = tid; d < dF; d += 256) {
        float acc = 0.f;
        for (int i = 0; i < kk; ++i)
            acc += s_w[i] * feat[(size_t)s_ord[i] * dF + d];
        out[(size_t)b * dF + d] = acc;
    }
    if (tid == 0 && out_size >= B * dF + B)
        out[(size_t)B * dF + b] = s_tres;
}

// ---------------------------------------------------------------------------
extern "C" void kernel_launch(void* const* d_in, const int* in_sizes, int n_in,
                              void* d_out, int out_size) {
    const float* query     = (const float*)d_in[0];
    const float* mu        = (const float*)d_in[1];
    const float* log_var   = (const float*)d_in[2];
    const float* raw_alpha = (const float*)d_in[3];
    const float* features  = (const float*)d_in[4];
    const float* log_tau   = (const float*)d_in[5];
    const int*   kptr      = (n_in >= 7) ? (const int*)d_in[6] : nullptr;

    int B  = in_sizes[0] / DS;     // 1024
    int N  = in_sizes[1] / DS;     // 131072
    int dF = in_sizes[4] / N;      // 256
    float* out = (float*)d_out;

    prep_blob<<<N / PB_TILE, 256>>>(mu, log_var, raw_alpha, N);
    prep_query<<<(DS * B + 255) / 256, 256>>>(query, B);

    dim3 ggrid(B / 64, N / 128);   // q-tiles fast => W reuse in L2
    gemm_t_kernel<<<ggrid, 256>>>(B, N);

    topk_kernel<<<B, 256>>>(B, N);

    composite_kernel<<<B, 256>>>(query, mu, log_var, raw_alpha, features,
                                 log_tau, kptr, out, B, dF, out_size);
}